// round 15
// baseline (speedup 1.0000x reference)
#include <cuda_runtime.h>
#include <cuda_bf16.h>
#include <cstdint>

// ---------------------------------------------------------------------------
// Problem constants
// ---------------------------------------------------------------------------
#define N_NODES   100000
#define BATCH     4
#define CH        128
#define M_TOTAL   (BATCH * N_NODES)    // 400000
#define TILE_M    128
#define N_TILES   (M_TOTAL / TILE_M)   // 3125
#define DECAYF    0.7f
#define LN_EPSF   1e-5f

// ---------------------------------------------------------------------------
// Device scratch
// ---------------------------------------------------------------------------
__device__ __align__(16) float g_w0[M_TOTAL];
__device__ __align__(16) float g_it0[N_NODES * BATCH];           // [n][b]
__device__ __align__(16) float g_it1[N_NODES * BATCH];
__device__ __align__(16) float g_it2[N_NODES * BATCH];

// ---------------------------------------------------------------------------
// PTX helpers (baseline PTX — bare sm_103 target)
// ---------------------------------------------------------------------------
__device__ __forceinline__ uint32_t smem_u32(const void* p) {
    uint32_t a;
    asm("{ .reg .u64 t; cvta.to.shared.u64 t, %1; cvt.u32.u64 %0, t; }" : "=r"(a) : "l"(p));
    return a;
}
#define CP_ASYNC16(dst_u32, src_ptr) \
    asm volatile("cp.async.cg.shared.global [%0], [%1], 16;" :: "r"(dst_u32), "l"(src_ptr))
#define CP_COMMIT() asm volatile("cp.async.commit_group;" ::: "memory")
#define CP_WAIT0()  asm volatile("cp.async.wait_group 0;" ::: "memory")

__device__ __forceinline__ void mma_bf16(float* c, const uint32_t* a, const uint32_t* b) {
    asm volatile(
        "mma.sync.aligned.m16n8k16.row.col.f32.bf16.bf16.f32 "
        "{%0,%1,%2,%3}, {%4,%5,%6,%7}, {%8,%9}, {%0,%1,%2,%3};"
        : "+f"(c[0]), "+f"(c[1]), "+f"(c[2]), "+f"(c[3])
        : "r"(a[0]), "r"(a[1]), "r"(a[2]), "r"(a[3]), "r"(b[0]), "r"(b[1]));
}
__device__ __forceinline__ void ldsm_x4(uint32_t addr, uint32_t& r0, uint32_t& r1,
                                        uint32_t& r2, uint32_t& r3) {
    asm volatile("ldmatrix.sync.aligned.m8n8.x4.shared.b16 {%0,%1,%2,%3}, [%4];"
                 : "=r"(r0), "=r"(r1), "=r"(r2), "=r"(r3) : "r"(addr));
}
// BF16X3 rn-split of float2 -> packed bf16x2 hi/lo (low half = .x)
__device__ __forceinline__ void split_pair(float2 p, uint32_t& hi, uint32_t& lo) {
    uint32_t h;
    asm("cvt.rn.bf16x2.f32 %0, %1, %2;" : "=r"(h) : "f"(p.y), "f"(p.x));
    float hx = __uint_as_float(h << 16);
    float hy = __uint_as_float(h & 0xffff0000u);
    uint32_t l;
    asm("cvt.rn.bf16x2.f32 %0, %1, %2;" : "=r"(l) : "f"(p.y - hy), "f"(p.x - hx));
    hi = h; lo = l;
}

// ---------------------------------------------------------------------------
// SMEM layouts (bytes). stride 136 bf16 = 272 B/row -> ldmatrix conflict-free
// ---------------------------------------------------------------------------
#define AK_STRIDE    136
#define STAGE_BYTES  (128 * 128 * 4)                  // 65536
#define APLANE_BYTES (128 * AK_STRIDE * 2)            // 34816

// kq kernel: stage + A planes + B planes (32 rows)
#define KQ_BPLANE_BYTES (32 * AK_STRIDE * 2)          // 8704
#define KQ_OFF_AH  STAGE_BYTES
#define KQ_OFF_AL  (KQ_OFF_AH + APLANE_BYTES)
#define KQ_OFF_BH  (KQ_OFF_AL + APLANE_BYTES)
#define KQ_OFF_BL  (KQ_OFF_BH + KQ_BPLANE_BYTES)
#define KQ_SMEM    (KQ_OFF_BL + KQ_BPLANE_BYTES)      // 152576

// fused kernel: stage + A planes + B planes (128 rows) + stats
#define FV_BPLANE_BYTES (128 * AK_STRIDE * 2)         // 34816
#define FV_OFF_AH  STAGE_BYTES
#define FV_OFF_AL  (FV_OFF_AH + APLANE_BYTES)
#define FV_OFF_BH  (FV_OFF_AL + APLANE_BYTES)
#define FV_OFF_BL  (FV_OFF_BH + FV_BPLANE_BYTES)
#define FV_OFF_ST  (FV_OFF_BL + FV_BPLANE_BYTES)      // stats: 2 x 128 float2
#define FV_SMEM    (FV_OFF_ST + 128 * 2 * 8)          // 206848

// ---------------------------------------------------------------------------
// Kernel 1: kq projection GEMM (N=32), BF16X3 -> w0[m] = mean_k(key*query)
// 8 warps, each: 16 rows x 32 cols (nt=4)
// ---------------------------------------------------------------------------
__global__ void __launch_bounds__(256, 1)
kq_gemm_kernel(const float* __restrict__ x, const float* __restrict__ Wk,
               const float* __restrict__ Wq) {
    extern __shared__ char smem[];
    float* Stage = reinterpret_cast<float*>(smem);
    __nv_bfloat16* Ah = reinterpret_cast<__nv_bfloat16*>(smem + KQ_OFF_AH);
    __nv_bfloat16* Al = reinterpret_cast<__nv_bfloat16*>(smem + KQ_OFF_AL);
    __nv_bfloat16* Bh = reinterpret_cast<__nv_bfloat16*>(smem + KQ_OFF_BH);
    __nv_bfloat16* Bl = reinterpret_cast<__nv_bfloat16*>(smem + KQ_OFF_BL);

    const int tid  = threadIdx.x;
    const int wid  = tid >> 5;
    const int lane = tid & 31;
    const int lr   = lane >> 2;
    const int lc   = lane & 3;
    const uint32_t sb = smem_u32(smem);

    // B planes = split([Wk(16); Wq(16)])
    for (int idx = tid; idx < 32 * 64; idx += 256) {
        int n  = idx >> 6;
        int k2 = (idx & 63) * 2;
        const float* srcrow = (n < 16) ? (Wk + n * CH) : (Wq + (n - 16) * CH);
        float2 p = *reinterpret_cast<const float2*>(srcrow + k2);
        uint32_t h, l;
        split_pair(p, h, l);
        *reinterpret_cast<uint32_t*>(Bh + n * AK_STRIDE + k2) = h;
        *reinterpret_cast<uint32_t*>(Bl + n * AK_STRIDE + k2) = l;
    }

    // ldmatrix lane addresses
    const int lm_m = lane >> 3, lm_r = lane & 7;
    uint32_t a_addr[2];
    {
        int row = wid * 16 + (lm_m & 1) * 8 + lm_r;
        int kof = (lm_m >> 1) * 8;
        a_addr[0] = sb + KQ_OFF_AH + (uint32_t)(row * AK_STRIDE + kof) * 2;
        a_addr[1] = sb + KQ_OFF_AL + (uint32_t)(row * AK_STRIDE + kof) * 2;
    }
    uint32_t b_addr[2][2];   // [pair][plane]
    #pragma unroll
    for (int p = 0; p < 2; p++) {
        int n   = p * 16 + (lm_m >> 1) * 8 + lm_r;
        int kof = (lm_m & 1) * 8;
        b_addr[p][0] = sb + KQ_OFF_BH + (uint32_t)(n * AK_STRIDE + kof) * 2;
        b_addr[p][1] = sb + KQ_OFF_BL + (uint32_t)(n * AK_STRIDE + kof) * 2;
    }

    const int tile0  = blockIdx.x;
    const int stride = gridDim.x;

    auto prefetch = [&](int tile) {
        const float* src = x + (size_t)tile * TILE_M * CH;
        #pragma unroll 4
        for (int idx = tid; idx < TILE_M * 32; idx += 256)
            CP_ASYNC16(sb + (uint32_t)idx * 16, src + idx * 4);
        CP_COMMIT();
    };
    auto split_stage = [&]() {
        #pragma unroll 4
        for (int idx = tid; idx < 128 * 64; idx += 256) {
            int row = idx >> 6;
            int k2  = (idx & 63) * 2;
            float2 p = *reinterpret_cast<const float2*>(Stage + row * 128 + k2);
            uint32_t h, l;
            split_pair(p, h, l);
            *reinterpret_cast<uint32_t*>(Ah + row * AK_STRIDE + k2) = h;
            *reinterpret_cast<uint32_t*>(Al + row * AK_STRIDE + k2) = l;
        }
    };

    if (tile0 < N_TILES) prefetch(tile0);
    CP_WAIT0();
    __syncthreads();
    if (tile0 < N_TILES) split_stage();
    __syncthreads();
    if (tile0 + stride < N_TILES) prefetch(tile0 + stride);

    for (int tile = tile0; tile < N_TILES; tile += stride) {
        float acc[4][4];
        #pragma unroll
        for (int nt = 0; nt < 4; nt++)
            #pragma unroll
            for (int j = 0; j < 4; j++) acc[nt][j] = 0.0f;

        #pragma unroll
        for (int ks = 0; ks < 8; ks++) {
            const uint32_t kb = ks * 32;
            uint32_t ah[4], al[4], bh[4][2], bl[4][2];
            ldsm_x4(a_addr[0] + kb, ah[0], ah[1], ah[2], ah[3]);
            ldsm_x4(a_addr[1] + kb, al[0], al[1], al[2], al[3]);
            #pragma unroll
            for (int p = 0; p < 2; p++) {
                ldsm_x4(b_addr[p][0] + kb, bh[2*p][0], bh[2*p][1], bh[2*p+1][0], bh[2*p+1][1]);
                ldsm_x4(b_addr[p][1] + kb, bl[2*p][0], bl[2*p][1], bl[2*p+1][0], bl[2*p+1][1]);
            }
            #pragma unroll
            for (int nt = 0; nt < 4; nt++) {
                mma_bf16(acc[nt], al, bh[nt]);
                mma_bf16(acc[nt], ah, bl[nt]);
                mma_bf16(acc[nt], ah, bh[nt]);
            }
        }

        // key: nt 0,1 (cols 0..15); query: nt 2,3 (cols 16..31), same slot layout
        float pr  = acc[0][0] * acc[2][0] + acc[0][1] * acc[2][1]
                  + acc[1][0] * acc[3][0] + acc[1][1] * acc[3][1];
        float pr8 = acc[0][2] * acc[2][2] + acc[0][3] * acc[2][3]
                  + acc[1][2] * acc[3][2] + acc[1][3] * acc[3][3];
        pr  += __shfl_xor_sync(0xFFFFFFFFu, pr, 1);
        pr  += __shfl_xor_sync(0xFFFFFFFFu, pr, 2);
        pr8 += __shfl_xor_sync(0xFFFFFFFFu, pr8, 1);
        pr8 += __shfl_xor_sync(0xFFFFFFFFu, pr8, 2);
        if (lc == 0) {
            int ma = tile * TILE_M + wid * 16 + lr;
            int mb = ma + 8;
            float w0a = pr * (1.0f / 16.0f);
            float w0b = pr8 * (1.0f / 16.0f);
            g_w0[ma] = w0a;
            g_w0[mb] = w0b;
            int ba = ma / N_NODES, na = ma - ba * N_NODES;
            int bb = mb / N_NODES, nb = mb - bb * N_NODES;
            g_it0[na * 4 + ba] = w0a;
            g_it0[nb * 4 + bb] = w0b;
        }

        __syncthreads();
        if (tile + stride < N_TILES) {
            CP_WAIT0();
            __syncthreads();
            split_stage();
            __syncthreads();
            if (tile + 2 * stride < N_TILES) prefetch(tile + 2 * stride);
        }
    }
}

// ---------------------------------------------------------------------------
// Kernel 2: zero iteration buffers
// ---------------------------------------------------------------------------
__global__ void zero_kernel() {
    int i = blockIdx.x * blockDim.x + threadIdx.x;
    int stride = gridDim.x * blockDim.x;
    for (; i < N_NODES * BATCH; i += stride) {
        g_it1[i] = 0.0f;
        g_it2[i] = 0.0f;
    }
}

// ---------------------------------------------------------------------------
// Kernel 3: SpMM iteration via vector red: one 16B RMW per edge
// ---------------------------------------------------------------------------
__global__ void spmm_kernel(const int* __restrict__ ei,
                            const float* __restrict__ ev, int E, int stage) {
    const float* __restrict__ in = (stage == 0) ? g_it0 : g_it1;
    float* __restrict__ out      = (stage == 0) ? g_it1 : g_it2;
    int e = blockIdx.x * blockDim.x + threadIdx.x;
    int stride = gridDim.x * blockDim.x;
    for (; e < E; e += stride) {
        int r = __ldg(ei + e);
        int c = __ldg(ei + E + e);
        float v = __ldg(ev + e) * DECAYF;
        float4 w = *reinterpret_cast<const float4*>(in + 4 * c);
        asm volatile("red.global.add.v4.f32 [%0], {%1, %2, %3, %4};"
                     :: "l"(out + 4 * r),
                        "f"(v * w.x), "f"(v * w.y), "f"(v * w.z), "f"(v * w.w)
                     : "memory");
    }
}

// ---------------------------------------------------------------------------
// Kernel 4: fused values GEMM (N=128, BF16X3) + scale-invariant LayerNorm
//   v = x @ Wv^T (in accumulators);  out = (v-mu)*w*rsqrt(w^2*var+eps)*g + b
// 8 warps: warpM = wid>>1 (4 x 32 rows), warpN = wid&1 (2 x 64 cols, nt=8)
// ---------------------------------------------------------------------------
__global__ void __launch_bounds__(256, 1)
fused_values_ln_kernel(const float* __restrict__ x, const float* __restrict__ Wv,
                       const float* __restrict__ gamma, const float* __restrict__ beta,
                       float* __restrict__ out) {
    extern __shared__ char smem[];
    float* Stage = reinterpret_cast<float*>(smem);
    __nv_bfloat16* Ah = reinterpret_cast<__nv_bfloat16*>(smem + FV_OFF_AH);
    __nv_bfloat16* Al = reinterpret_cast<__nv_bfloat16*>(smem + FV_OFF_AL);
    __nv_bfloat16* Bh = reinterpret_cast<__nv_bfloat16*>(smem + FV_OFF_BH);
    __nv_bfloat16* Bl = reinterpret_cast<__nv_bfloat16*>(smem + FV_OFF_BL);
    float2* StatsA = reinterpret_cast<float2*>(smem + FV_OFF_ST);        // warpN=0
    float2* StatsB = StatsA + 128;                                       // warpN=1

    const int tid   = threadIdx.x;
    const int wid   = tid >> 5;
    const int lane  = tid & 31;
    const int warpM = wid >> 1;
    const int warpN = wid & 1;
    const int lr    = lane >> 2;
    const int lc    = lane & 3;
    const uint32_t sb = smem_u32(smem);

    // B planes = split(Wv)
    for (int idx = tid; idx < 128 * 64; idx += 256) {
        int n  = idx >> 6;
        int k2 = (idx & 63) * 2;
        float2 p = *reinterpret_cast<const float2*>(Wv + n * CH + k2);
        uint32_t h, l;
        split_pair(p, h, l);
        *reinterpret_cast<uint32_t*>(Bh + n * AK_STRIDE + k2) = h;
        *reinterpret_cast<uint32_t*>(Bl + n * AK_STRIDE + k2) = l;
    }

    // gamma/beta for this lane's columns
    float2 ga[8], be[8];
    #pragma unroll
    for (int nt = 0; nt < 8; nt++) {
        int col = warpN * 64 + nt * 8 + 2 * lc;
        ga[nt] = *reinterpret_cast<const float2*>(gamma + col);
        be[nt] = *reinterpret_cast<const float2*>(beta + col);
    }

    // ldmatrix lane addresses
    const int lm_m = lane >> 3, lm_r = lane & 7;
    uint32_t a_addr[2][2];
    #pragma unroll
    for (int mt = 0; mt < 2; mt++) {
        int row = warpM * 32 + mt * 16 + (lm_m & 1) * 8 + lm_r;
        int kof = (lm_m >> 1) * 8;
        a_addr[mt][0] = sb + FV_OFF_AH + (uint32_t)(row * AK_STRIDE + kof) * 2;
        a_addr[mt][1] = sb + FV_OFF_AL + (uint32_t)(row * AK_STRIDE + kof) * 2;
    }
    uint32_t b_addr[4][2];
    #pragma unroll
    for (int p = 0; p < 4; p++) {
        int n   = warpN * 64 + p * 16 + (lm_m >> 1) * 8 + lm_r;
        int kof = (lm_m & 1) * 8;
        b_addr[p][0] = sb + FV_OFF_BH + (uint32_t)(n * AK_STRIDE + kof) * 2;
        b_addr[p][1] = sb + FV_OFF_BL + (uint32_t)(n * AK_STRIDE + kof) * 2;
    }

    const int tile0  = blockIdx.x;
    const int stride = gridDim.x;

    auto prefetch = [&](int tile) {
        const float* src = x + (size_t)tile * TILE_M * CH;
        #pragma unroll 4
        for (int idx = tid; idx < TILE_M * 32; idx += 256)
            CP_ASYNC16(sb + (uint32_t)idx * 16, src + idx * 4);
        CP_COMMIT();
    };
    auto split_stage = [&]() {
        #pragma unroll 4
        for (int idx = tid; idx < 128 * 64; idx += 256) {
            int row = idx >> 6;
            int k2  = (idx & 63) * 2;
            float2 p = *reinterpret_cast<const float2*>(Stage + row * 128 + k2);
            uint32_t h, l;
            split_pair(p, h, l);
            *reinterpret_cast<uint32_t*>(Ah + row * AK_STRIDE + k2) = h;
            *reinterpret_cast<uint32_t*>(Al + row * AK_STRIDE + k2) = l;
        }
    };

    if (tile0 < N_TILES) prefetch(tile0);
    CP_WAIT0();
    __syncthreads();
    if (tile0 < N_TILES) split_stage();
    __syncthreads();
    if (tile0 + stride < N_TILES) prefetch(tile0 + stride);

    for (int tile = tile0; tile < N_TILES; tile += stride) {
        float acc[2][8][4];
        #pragma unroll
        for (int mt = 0; mt < 2; mt++)
            #pragma unroll
            for (int nt = 0; nt < 8; nt++)
                #pragma unroll
                for (int j = 0; j < 4; j++) acc[mt][nt][j] = 0.0f;

        #pragma unroll
        for (int ks = 0; ks < 8; ks++) {
            const uint32_t kb = ks * 32;
            uint32_t bh[8][2], bl[8][2];
            #pragma unroll
            for (int p = 0; p < 4; p++) {
                ldsm_x4(b_addr[p][0] + kb, bh[2*p][0], bh[2*p][1], bh[2*p+1][0], bh[2*p+1][1]);
                ldsm_x4(b_addr[p][1] + kb, bl[2*p][0], bl[2*p][1], bl[2*p+1][0], bl[2*p+1][1]);
            }
            uint32_t ah[2][4], al[2][4];
            #pragma unroll
            for (int mt = 0; mt < 2; mt++) {
                ldsm_x4(a_addr[mt][0] + kb, ah[mt][0], ah[mt][1], ah[mt][2], ah[mt][3]);
                ldsm_x4(a_addr[mt][1] + kb, al[mt][0], al[mt][1], al[mt][2], al[mt][3]);
            }
            #pragma unroll
            for (int mt = 0; mt < 2; mt++)
                #pragma unroll
                for (int nt = 0; nt < 8; nt++) {
                    mma_bf16(acc[mt][nt], al[mt], bh[nt]);
                    mma_bf16(acc[mt][nt], ah[mt], bl[nt]);
                    mma_bf16(acc[mt][nt], ah[mt], bh[nt]);
                }
        }

        // ---- Epilogue: per-row stats across both warpN halves ----
        #pragma unroll
        for (int mt = 0; mt < 2; mt++) {
            float sl = 0.f, ql = 0.f, sh = 0.f, qh = 0.f;
            #pragma unroll
            for (int nt = 0; nt < 8; nt++) {
                sl += acc[mt][nt][0] + acc[mt][nt][1];
                ql += acc[mt][nt][0] * acc[mt][nt][0] + acc[mt][nt][1] * acc[mt][nt][1];
                sh += acc[mt][nt][2] + acc[mt][nt][3];
                qh += acc[mt][nt][2] * acc[mt][nt][2] + acc[mt][nt][3] * acc[mt][nt][3];
            }
            #pragma unroll
            for (int o = 1; o <= 2; o <<= 1) {
                sl += __shfl_xor_sync(0xFFFFFFFFu, sl, o);
                ql += __shfl_xor_sync(0xFFFFFFFFu, ql, o);
                sh += __shfl_xor_sync(0xFFFFFFFFu, sh, o);
                qh += __shfl_xor_sync(0xFFFFFFFFu, qh, o);
            }
            if (lc == 0) {
                int rlo = warpM * 32 + mt * 16 + lr;
                float2* st = (warpN == 0) ? StatsA : StatsB;
                st[rlo]     = make_float2(sl, ql);
                st[rlo + 8] = make_float2(sh, qh);
            }
        }
        __syncthreads();

        #pragma unroll
        for (int mt = 0; mt < 2; mt++) {
            int rlo = warpM * 32 + mt * 16 + lr;   // tile-local rows rlo, rlo+8
            #pragma unroll
            for (int half = 0; half < 2; half++) {
                int rloc = rlo + half * 8;
                int m = tile * TILE_M + rloc;
                float2 s0 = StatsA[rloc], s1 = StatsB[rloc];
                float mu  = (s0.x + s1.x) * (1.0f / 128.0f);
                float var = (s0.y + s1.y) * (1.0f / 128.0f) - mu * mu;
                int b = m / N_NODES;
                int n = m - b * N_NODES;
                float w = g_w0[m] + g_it1[n * 4 + b] + g_it2[n * 4 + b];
                float scale = w * rsqrtf(w * w * var + LN_EPSF);
                float* orow = out + (size_t)m * CH;
                #pragma unroll
                for (int nt = 0; nt < 8; nt++) {
                    int col = warpN * 64 + nt * 8 + 2 * lc;
                    float v0 = acc[mt][nt][half * 2 + 0];
                    float v1 = acc[mt][nt][half * 2 + 1];
                    float2 o2;
                    o2.x = (v0 - mu) * scale * ga[nt].x + be[nt].x;
                    o2.y = (v1 - mu) * scale * ga[nt].y + be[nt].y;
                    *reinterpret_cast<float2*>(orow + col) = o2;
                }
            }
        }

        // ---- Advance pipeline ----
        __syncthreads();
        if (tile + stride < N_TILES) {
            CP_WAIT0();
            __syncthreads();
            split_stage();
            __syncthreads();
            if (tile + 2 * stride < N_TILES) prefetch(tile + 2 * stride);
        }
    }
}

// ---------------------------------------------------------------------------
// kernel_launch
// Inputs: x, W_k, W_q, W_v, ln_gamma, ln_beta, edge_vals, edge_index
// ---------------------------------------------------------------------------
extern "C" void kernel_launch(void* const* d_in, const int* in_sizes, int n_in,
                              void* d_out, int out_size) {
    const float* x      = (const float*)d_in[0];
    const float* Wk     = (const float*)d_in[1];
    const float* Wq     = (const float*)d_in[2];
    const float* Wv     = (const float*)d_in[3];
    const float* gamma  = (const float*)d_in[4];
    const float* beta   = (const float*)d_in[5];
    const float* ev     = (const float*)d_in[6];
    const int*   ei     = (const int*)d_in[7];
    int E = in_sizes[6];

    cudaFuncSetAttribute((const void*)kq_gemm_kernel,
                         cudaFuncAttributeMaxDynamicSharedMemorySize, KQ_SMEM);
    cudaFuncSetAttribute((const void*)fused_values_ln_kernel,
                         cudaFuncAttributeMaxDynamicSharedMemorySize, FV_SMEM);

    zero_kernel<<<128, 256>>>();
    kq_gemm_kernel<<<148, 256, KQ_SMEM>>>(x, Wk, Wq);
    spmm_kernel<<<2048, 256>>>(ei, ev, E, 0);
    spmm_kernel<<<2048, 256>>>(ei, ev, E, 1);
    fused_values_ln_kernel<<<148, 256, FV_SMEM>>>(x, Wv, gamma, beta, (float*)d_out);
}

// round 16
// speedup vs baseline: 1.0066x; 1.0066x over previous
#include <cuda_runtime.h>
#include <cuda_bf16.h>
#include <cstdint>

// ---------------------------------------------------------------------------
// Problem constants
// ---------------------------------------------------------------------------
#define N_NODES   100000
#define BATCH     4
#define CH        128
#define M_TOTAL   (BATCH * N_NODES)    // 400000
#define TILE_M    128
#define N_TILES   (M_TOTAL / TILE_M)   // 3125
#define DECAYF    0.7f
#define LN_EPSF   1e-5f

// ---------------------------------------------------------------------------
// Device scratch
// ---------------------------------------------------------------------------
__device__ __align__(16) float g_w0[M_TOTAL];
__device__ __align__(16) float g_it0[N_NODES * BATCH];           // [n][b]
__device__ __align__(16) float g_it1[N_NODES * BATCH];
__device__ __align__(16) float g_it2[N_NODES * BATCH];

// ---------------------------------------------------------------------------
// PTX helpers (baseline PTX — bare sm_103 target)
// ---------------------------------------------------------------------------
__device__ __forceinline__ uint32_t smem_u32(const void* p) {
    uint32_t a;
    asm("{ .reg .u64 t; cvta.to.shared.u64 t, %1; cvt.u32.u64 %0, t; }" : "=r"(a) : "l"(p));
    return a;
}
#define CP_ASYNC16(dst_u32, src_ptr) \
    asm volatile("cp.async.cg.shared.global [%0], [%1], 16;" :: "r"(dst_u32), "l"(src_ptr))
#define CP_COMMIT() asm volatile("cp.async.commit_group;" ::: "memory")
#define CP_WAIT0()  asm volatile("cp.async.wait_group 0;" ::: "memory")

__device__ __forceinline__ void mma_bf16(float* c, const uint32_t* a, const uint32_t* b) {
    asm volatile(
        "mma.sync.aligned.m16n8k16.row.col.f32.bf16.bf16.f32 "
        "{%0,%1,%2,%3}, {%4,%5,%6,%7}, {%8,%9}, {%0,%1,%2,%3};"
        : "+f"(c[0]), "+f"(c[1]), "+f"(c[2]), "+f"(c[3])
        : "r"(a[0]), "r"(a[1]), "r"(a[2]), "r"(a[3]), "r"(b[0]), "r"(b[1]));
}
__device__ __forceinline__ void ldsm_x4(uint32_t addr, uint32_t& r0, uint32_t& r1,
                                        uint32_t& r2, uint32_t& r3) {
    asm volatile("ldmatrix.sync.aligned.m8n8.x4.shared.b16 {%0,%1,%2,%3}, [%4];"
                 : "=r"(r0), "=r"(r1), "=r"(r2), "=r"(r3) : "r"(addr));
}
// BF16X3 rn-split of float2 -> packed bf16x2 hi/lo (low half = .x)
__device__ __forceinline__ void split_pair(float2 p, uint32_t& hi, uint32_t& lo) {
    uint32_t h;
    asm("cvt.rn.bf16x2.f32 %0, %1, %2;" : "=r"(h) : "f"(p.y), "f"(p.x));
    float hx = __uint_as_float(h << 16);
    float hy = __uint_as_float(h & 0xffff0000u);
    uint32_t l;
    asm("cvt.rn.bf16x2.f32 %0, %1, %2;" : "=r"(l) : "f"(p.y - hy), "f"(p.x - hx));
    hi = h; lo = l;
}

// ---------------------------------------------------------------------------
// SMEM layouts (bytes). stride 136 bf16 = 272 B/row -> ldmatrix conflict-free
// ---------------------------------------------------------------------------
#define AK_STRIDE    136
#define STAGE_BYTES  (128 * 128 * 4)                  // 65536
#define APLANE_BYTES (128 * AK_STRIDE * 2)            // 34816

// kq kernel: stage + A planes + B planes (32 rows)
#define KQ_BPLANE_BYTES (32 * AK_STRIDE * 2)          // 8704
#define KQ_OFF_AH  STAGE_BYTES
#define KQ_OFF_AL  (KQ_OFF_AH + APLANE_BYTES)
#define KQ_OFF_BH  (KQ_OFF_AL + APLANE_BYTES)
#define KQ_OFF_BL  (KQ_OFF_BH + KQ_BPLANE_BYTES)
#define KQ_SMEM    (KQ_OFF_BL + KQ_BPLANE_BYTES)      // 152576

// fused kernel: stage + A planes + B planes (128 rows) + stats
#define FV_BPLANE_BYTES (128 * AK_STRIDE * 2)         // 34816
#define FV_OFF_AH  STAGE_BYTES
#define FV_OFF_AL  (FV_OFF_AH + APLANE_BYTES)
#define FV_OFF_BH  (FV_OFF_AL + APLANE_BYTES)
#define FV_OFF_BL  (FV_OFF_BH + FV_BPLANE_BYTES)
#define FV_OFF_ST  (FV_OFF_BL + FV_BPLANE_BYTES)      // stats: 2 x 128 float2
#define FV_SMEM    (FV_OFF_ST + 128 * 2 * 8)          // 206848

// ---------------------------------------------------------------------------
// Kernel 1: kq projection GEMM (N=32), BF16X3 -> w0[m] = mean_k(key*query)
// 8 warps, each: 16 rows x 32 cols (nt=4)
// ---------------------------------------------------------------------------
__global__ void __launch_bounds__(256, 1)
kq_gemm_kernel(const float* __restrict__ x, const float* __restrict__ Wk,
               const float* __restrict__ Wq) {
    extern __shared__ char smem[];
    float* Stage = reinterpret_cast<float*>(smem);
    __nv_bfloat16* Ah = reinterpret_cast<__nv_bfloat16*>(smem + KQ_OFF_AH);
    __nv_bfloat16* Al = reinterpret_cast<__nv_bfloat16*>(smem + KQ_OFF_AL);
    __nv_bfloat16* Bh = reinterpret_cast<__nv_bfloat16*>(smem + KQ_OFF_BH);
    __nv_bfloat16* Bl = reinterpret_cast<__nv_bfloat16*>(smem + KQ_OFF_BL);

    const int tid  = threadIdx.x;
    const int wid  = tid >> 5;
    const int lane = tid & 31;
    const int lr   = lane >> 2;
    const int lc   = lane & 3;
    const uint32_t sb = smem_u32(smem);

    // B planes = split([Wk(16); Wq(16)])
    for (int idx = tid; idx < 32 * 64; idx += 256) {
        int n  = idx >> 6;
        int k2 = (idx & 63) * 2;
        const float* srcrow = (n < 16) ? (Wk + n * CH) : (Wq + (n - 16) * CH);
        float2 p = *reinterpret_cast<const float2*>(srcrow + k2);
        uint32_t h, l;
        split_pair(p, h, l);
        *reinterpret_cast<uint32_t*>(Bh + n * AK_STRIDE + k2) = h;
        *reinterpret_cast<uint32_t*>(Bl + n * AK_STRIDE + k2) = l;
    }

    // ldmatrix lane addresses
    const int lm_m = lane >> 3, lm_r = lane & 7;
    uint32_t a_addr[2];
    {
        int row = wid * 16 + (lm_m & 1) * 8 + lm_r;
        int kof = (lm_m >> 1) * 8;
        a_addr[0] = sb + KQ_OFF_AH + (uint32_t)(row * AK_STRIDE + kof) * 2;
        a_addr[1] = sb + KQ_OFF_AL + (uint32_t)(row * AK_STRIDE + kof) * 2;
    }
    uint32_t b_addr[2][2];   // [pair][plane]
    #pragma unroll
    for (int p = 0; p < 2; p++) {
        int n   = p * 16 + (lm_m >> 1) * 8 + lm_r;
        int kof = (lm_m & 1) * 8;
        b_addr[p][0] = sb + KQ_OFF_BH + (uint32_t)(n * AK_STRIDE + kof) * 2;
        b_addr[p][1] = sb + KQ_OFF_BL + (uint32_t)(n * AK_STRIDE + kof) * 2;
    }

    const int tile0  = blockIdx.x;
    const int stride = gridDim.x;

    auto prefetch = [&](int tile) {
        const float* src = x + (size_t)tile * TILE_M * CH;
        #pragma unroll 4
        for (int idx = tid; idx < TILE_M * 32; idx += 256)
            CP_ASYNC16(sb + (uint32_t)idx * 16, src + idx * 4);
        CP_COMMIT();
    };
    auto split_stage = [&]() {
        #pragma unroll 4
        for (int idx = tid; idx < 128 * 64; idx += 256) {
            int row = idx >> 6;
            int k2  = (idx & 63) * 2;
            float2 p = *reinterpret_cast<const float2*>(Stage + row * 128 + k2);
            uint32_t h, l;
            split_pair(p, h, l);
            *reinterpret_cast<uint32_t*>(Ah + row * AK_STRIDE + k2) = h;
            *reinterpret_cast<uint32_t*>(Al + row * AK_STRIDE + k2) = l;
        }
    };

    if (tile0 < N_TILES) prefetch(tile0);
    CP_WAIT0();
    __syncthreads();
    if (tile0 < N_TILES) split_stage();
    __syncthreads();
    if (tile0 + stride < N_TILES) prefetch(tile0 + stride);

    for (int tile = tile0; tile < N_TILES; tile += stride) {
        float acc[4][4];
        #pragma unroll
        for (int nt = 0; nt < 4; nt++)
            #pragma unroll
            for (int j = 0; j < 4; j++) acc[nt][j] = 0.0f;

        #pragma unroll
        for (int ks = 0; ks < 8; ks++) {
            const uint32_t kb = ks * 32;
            uint32_t ah[4], al[4], bh[4][2], bl[4][2];
            ldsm_x4(a_addr[0] + kb, ah[0], ah[1], ah[2], ah[3]);
            ldsm_x4(a_addr[1] + kb, al[0], al[1], al[2], al[3]);
            #pragma unroll
            for (int p = 0; p < 2; p++) {
                ldsm_x4(b_addr[p][0] + kb, bh[2*p][0], bh[2*p][1], bh[2*p+1][0], bh[2*p+1][1]);
                ldsm_x4(b_addr[p][1] + kb, bl[2*p][0], bl[2*p][1], bl[2*p+1][0], bl[2*p+1][1]);
            }
            #pragma unroll
            for (int nt = 0; nt < 4; nt++) {
                mma_bf16(acc[nt], al, bh[nt]);
                mma_bf16(acc[nt], ah, bl[nt]);
                mma_bf16(acc[nt], ah, bh[nt]);
            }
        }

        // key: nt 0,1 (cols 0..15); query: nt 2,3 (cols 16..31), same slot layout
        float pr  = acc[0][0] * acc[2][0] + acc[0][1] * acc[2][1]
                  + acc[1][0] * acc[3][0] + acc[1][1] * acc[3][1];
        float pr8 = acc[0][2] * acc[2][2] + acc[0][3] * acc[2][3]
                  + acc[1][2] * acc[3][2] + acc[1][3] * acc[3][3];
        pr  += __shfl_xor_sync(0xFFFFFFFFu, pr, 1);
        pr  += __shfl_xor_sync(0xFFFFFFFFu, pr, 2);
        pr8 += __shfl_xor_sync(0xFFFFFFFFu, pr8, 1);
        pr8 += __shfl_xor_sync(0xFFFFFFFFu, pr8, 2);
        if (lc == 0) {
            int ma = tile * TILE_M + wid * 16 + lr;
            int mb = ma + 8;
            float w0a = pr * (1.0f / 16.0f);
            float w0b = pr8 * (1.0f / 16.0f);
            g_w0[ma] = w0a;
            g_w0[mb] = w0b;
            int ba = ma / N_NODES, na = ma - ba * N_NODES;
            int bb = mb / N_NODES, nb = mb - bb * N_NODES;
            g_it0[na * 4 + ba] = w0a;
            g_it0[nb * 4 + bb] = w0b;
        }

        __syncthreads();
        if (tile + stride < N_TILES) {
            CP_WAIT0();
            __syncthreads();
            split_stage();
            __syncthreads();
            if (tile + 2 * stride < N_TILES) prefetch(tile + 2 * stride);
        }
    }
}

// ---------------------------------------------------------------------------
// Kernel 2: zero iteration buffers
// ---------------------------------------------------------------------------
__global__ void zero_kernel() {
    int i = blockIdx.x * blockDim.x + threadIdx.x;
    int stride = gridDim.x * blockDim.x;
    for (; i < N_NODES * BATCH; i += stride) {
        g_it1[i] = 0.0f;
        g_it2[i] = 0.0f;
    }
}

// ---------------------------------------------------------------------------
// Kernel 3: SpMM iteration via vector red: one 16B RMW per edge
// ---------------------------------------------------------------------------
__global__ void spmm_kernel(const int* __restrict__ ei,
                            const float* __restrict__ ev, int E, int stage) {
    const float* __restrict__ in = (stage == 0) ? g_it0 : g_it1;
    float* __restrict__ out      = (stage == 0) ? g_it1 : g_it2;
    int e = blockIdx.x * blockDim.x + threadIdx.x;
    int stride = gridDim.x * blockDim.x;
    for (; e < E; e += stride) {
        int r = __ldg(ei + e);
        int c = __ldg(ei + E + e);
        float v = __ldg(ev + e) * DECAYF;
        float4 w = *reinterpret_cast<const float4*>(in + 4 * c);
        asm volatile("red.global.add.v4.f32 [%0], {%1, %2, %3, %4};"
                     :: "l"(out + 4 * r),
                        "f"(v * w.x), "f"(v * w.y), "f"(v * w.z), "f"(v * w.w)
                     : "memory");
    }
}

// ---------------------------------------------------------------------------
// Kernel 4: fused values GEMM (N=128, BF16X3) + scale-invariant LayerNorm
//   v = x @ Wv^T (in accumulators);  out = (v-mu)*w*rsqrt(w^2*var+eps)*g + b
// 8 warps: warpM = wid>>1 (4 x 32 rows), warpN = wid&1 (2 x 64 cols, nt=8)
// ---------------------------------------------------------------------------
__global__ void __launch_bounds__(256, 1)
fused_values_ln_kernel(const float* __restrict__ x, const float* __restrict__ Wv,
                       const float* __restrict__ gamma, const float* __restrict__ beta,
                       float* __restrict__ out) {
    extern __shared__ char smem[];
    float* Stage = reinterpret_cast<float*>(smem);
    __nv_bfloat16* Ah = reinterpret_cast<__nv_bfloat16*>(smem + FV_OFF_AH);
    __nv_bfloat16* Al = reinterpret_cast<__nv_bfloat16*>(smem + FV_OFF_AL);
    __nv_bfloat16* Bh = reinterpret_cast<__nv_bfloat16*>(smem + FV_OFF_BH);
    __nv_bfloat16* Bl = reinterpret_cast<__nv_bfloat16*>(smem + FV_OFF_BL);
    float2* StatsA = reinterpret_cast<float2*>(smem + FV_OFF_ST);        // warpN=0
    float2* StatsB = StatsA + 128;                                       // warpN=1

    const int tid   = threadIdx.x;
    const int wid   = tid >> 5;
    const int lane  = tid & 31;
    const int warpM = wid >> 1;
    const int warpN = wid & 1;
    const int lr    = lane >> 2;
    const int lc    = lane & 3;
    const uint32_t sb = smem_u32(smem);

    // B planes = split(Wv)
    for (int idx = tid; idx < 128 * 64; idx += 256) {
        int n  = idx >> 6;
        int k2 = (idx & 63) * 2;
        float2 p = *reinterpret_cast<const float2*>(Wv + n * CH + k2);
        uint32_t h, l;
        split_pair(p, h, l);
        *reinterpret_cast<uint32_t*>(Bh + n * AK_STRIDE + k2) = h;
        *reinterpret_cast<uint32_t*>(Bl + n * AK_STRIDE + k2) = l;
    }

    // gamma/beta for this lane's columns
    float2 ga[8], be[8];
    #pragma unroll
    for (int nt = 0; nt < 8; nt++) {
        int col = warpN * 64 + nt * 8 + 2 * lc;
        ga[nt] = *reinterpret_cast<const float2*>(gamma + col);
        be[nt] = *reinterpret_cast<const float2*>(beta + col);
    }

    // ldmatrix lane addresses
    const int lm_m = lane >> 3, lm_r = lane & 7;
    uint32_t a_addr[2][2];
    #pragma unroll
    for (int mt = 0; mt < 2; mt++) {
        int row = warpM * 32 + mt * 16 + (lm_m & 1) * 8 + lm_r;
        int kof = (lm_m >> 1) * 8;
        a_addr[mt][0] = sb + FV_OFF_AH + (uint32_t)(row * AK_STRIDE + kof) * 2;
        a_addr[mt][1] = sb + FV_OFF_AL + (uint32_t)(row * AK_STRIDE + kof) * 2;
    }
    uint32_t b_addr[4][2];
    #pragma unroll
    for (int p = 0; p < 4; p++) {
        int n   = warpN * 64 + p * 16 + (lm_m >> 1) * 8 + lm_r;
        int kof = (lm_m & 1) * 8;
        b_addr[p][0] = sb + FV_OFF_BH + (uint32_t)(n * AK_STRIDE + kof) * 2;
        b_addr[p][1] = sb + FV_OFF_BL + (uint32_t)(n * AK_STRIDE + kof) * 2;
    }

    const int tile0  = blockIdx.x;
    const int stride = gridDim.x;

    auto prefetch = [&](int tile) {
        const float* src = x + (size_t)tile * TILE_M * CH;
        #pragma unroll 4
        for (int idx = tid; idx < TILE_M * 32; idx += 256)
            CP_ASYNC16(sb + (uint32_t)idx * 16, src + idx * 4);
        CP_COMMIT();
    };
    auto split_stage = [&]() {
        #pragma unroll 4
        for (int idx = tid; idx < 128 * 64; idx += 256) {
            int row = idx >> 6;
            int k2  = (idx & 63) * 2;
            float2 p = *reinterpret_cast<const float2*>(Stage + row * 128 + k2);
            uint32_t h, l;
            split_pair(p, h, l);
            *reinterpret_cast<uint32_t*>(Ah + row * AK_STRIDE + k2) = h;
            *reinterpret_cast<uint32_t*>(Al + row * AK_STRIDE + k2) = l;
        }
    };

    if (tile0 < N_TILES) prefetch(tile0);
    CP_WAIT0();
    __syncthreads();
    if (tile0 < N_TILES) split_stage();
    __syncthreads();
    if (tile0 + stride < N_TILES) prefetch(tile0 + stride);

    for (int tile = tile0; tile < N_TILES; tile += stride) {
        float acc[2][8][4];
        #pragma unroll
        for (int mt = 0; mt < 2; mt++)
            #pragma unroll
            for (int nt = 0; nt < 8; nt++)
                #pragma unroll
                for (int j = 0; j < 4; j++) acc[mt][nt][j] = 0.0f;

        #pragma unroll
        for (int ks = 0; ks < 8; ks++) {
            const uint32_t kb = ks * 32;
            uint32_t bh[8][2], bl[8][2];
            #pragma unroll
            for (int p = 0; p < 4; p++) {
                ldsm_x4(b_addr[p][0] + kb, bh[2*p][0], bh[2*p][1], bh[2*p+1][0], bh[2*p+1][1]);
                ldsm_x4(b_addr[p][1] + kb, bl[2*p][0], bl[2*p][1], bl[2*p+1][0], bl[2*p+1][1]);
            }
            uint32_t ah[2][4], al[2][4];
            #pragma unroll
            for (int mt = 0; mt < 2; mt++) {
                ldsm_x4(a_addr[mt][0] + kb, ah[mt][0], ah[mt][1], ah[mt][2], ah[mt][3]);
                ldsm_x4(a_addr[mt][1] + kb, al[mt][0], al[mt][1], al[mt][2], al[mt][3]);
            }
            #pragma unroll
            for (int mt = 0; mt < 2; mt++)
                #pragma unroll
                for (int nt = 0; nt < 8; nt++) {
                    mma_bf16(acc[mt][nt], al[mt], bh[nt]);
                    mma_bf16(acc[mt][nt], ah[mt], bl[nt]);
                    mma_bf16(acc[mt][nt], ah[mt], bh[nt]);
                }
        }

        // ---- Epilogue: per-row stats across both warpN halves ----
        #pragma unroll
        for (int mt = 0; mt < 2; mt++) {
            float sl = 0.f, ql = 0.f, sh = 0.f, qh = 0.f;
            #pragma unroll
            for (int nt = 0; nt < 8; nt++) {
                sl += acc[mt][nt][0] + acc[mt][nt][1];
                ql += acc[mt][nt][0] * acc[mt][nt][0] + acc[mt][nt][1] * acc[mt][nt][1];
                sh += acc[mt][nt][2] + acc[mt][nt][3];
                qh += acc[mt][nt][2] * acc[mt][nt][2] + acc[mt][nt][3] * acc[mt][nt][3];
            }
            #pragma unroll
            for (int o = 1; o <= 2; o <<= 1) {
                sl += __shfl_xor_sync(0xFFFFFFFFu, sl, o);
                ql += __shfl_xor_sync(0xFFFFFFFFu, ql, o);
                sh += __shfl_xor_sync(0xFFFFFFFFu, sh, o);
                qh += __shfl_xor_sync(0xFFFFFFFFu, qh, o);
            }
            if (lc == 0) {
                int rlo = warpM * 32 + mt * 16 + lr;
                float2* st = (warpN == 0) ? StatsA : StatsB;
                st[rlo]     = make_float2(sl, ql);
                st[rlo + 8] = make_float2(sh, qh);
            }
        }
        __syncthreads();

        #pragma unroll
        for (int mt = 0; mt < 2; mt++) {
            int rlo = warpM * 32 + mt * 16 + lr;   // tile-local rows rlo, rlo+8
            #pragma unroll
            for (int half = 0; half < 2; half++) {
                int rloc = rlo + half * 8;
                int m = tile * TILE_M + rloc;
                float2 s0 = StatsA[rloc], s1 = StatsB[rloc];
                float mu  = (s0.x + s1.x) * (1.0f / 128.0f);
                float var = (s0.y + s1.y) * (1.0f / 128.0f) - mu * mu;
                int b = m / N_NODES;
                int n = m - b * N_NODES;
                float w = g_w0[m] + g_it1[n * 4 + b] + g_it2[n * 4 + b];
                float scale = w * rsqrtf(w * w * var + LN_EPSF);
                float* orow = out + (size_t)m * CH;
                #pragma unroll
                for (int nt = 0; nt < 8; nt++) {
                    int col = warpN * 64 + nt * 8 + 2 * lc;
                    float v0 = acc[mt][nt][half * 2 + 0];
                    float v1 = acc[mt][nt][half * 2 + 1];
                    float2 o2;
                    o2.x = (v0 - mu) * scale * ga[nt].x + be[nt].x;
                    o2.y = (v1 - mu) * scale * ga[nt].y + be[nt].y;
                    *reinterpret_cast<float2*>(orow + col) = o2;
                }
            }
        }

        // ---- Advance pipeline ----
        __syncthreads();
        if (tile + stride < N_TILES) {
            CP_WAIT0();
            __syncthreads();
            split_stage();
            __syncthreads();
            if (tile + 2 * stride < N_TILES) prefetch(tile + 2 * stride);
        }
    }
}

// ---------------------------------------------------------------------------
// kernel_launch
// Inputs: x, W_k, W_q, W_v, ln_gamma, ln_beta, edge_vals, edge_index
// ---------------------------------------------------------------------------
extern "C" void kernel_launch(void* const* d_in, const int* in_sizes, int n_in,
                              void* d_out, int out_size) {
    const float* x      = (const float*)d_in[0];
    const float* Wk     = (const float*)d_in[1];
    const float* Wq     = (const float*)d_in[2];
    const float* Wv     = (const float*)d_in[3];
    const float* gamma  = (const float*)d_in[4];
    const float* beta   = (const float*)d_in[5];
    const float* ev     = (const float*)d_in[6];
    const int*   ei     = (const int*)d_in[7];
    int E = in_sizes[6];

    cudaFuncSetAttribute((const void*)kq_gemm_kernel,
                         cudaFuncAttributeMaxDynamicSharedMemorySize, KQ_SMEM);
    cudaFuncSetAttribute((const void*)fused_values_ln_kernel,
                         cudaFuncAttributeMaxDynamicSharedMemorySize, FV_SMEM);

    zero_kernel<<<128, 256>>>();
    kq_gemm_kernel<<<148, 256, KQ_SMEM>>>(x, Wk, Wq);
    spmm_kernel<<<2048, 256>>>(ei, ev, E, 0);
    spmm_kernel<<<2048, 256>>>(ei, ev, E, 1);
    fused_values_ln_kernel<<<148, 256, FV_SMEM>>>(x, Wv, gamma, beta, (float*)d_out);
}